// round 17
// baseline (speedup 1.0000x reference)
#include <cuda_runtime.h>

typedef unsigned long long u64;

__device__ float4 g_c;  // {ta, tc, alpha/128, beta}

__device__ __forceinline__ float ex2f(float x) {
    float y;
    asm("ex2.approx.ftz.f32 %0, %1;" : "=f"(y) : "f"(x));
    return y;
}
__device__ __forceinline__ float cosf_hw(float x) {
    float y;
    asm("cos.approx.ftz.f32 %0, %1;" : "=f"(y) : "f"(x));
    return y;
}
__device__ __forceinline__ u64 pk2(float lo, float hi) {
    u64 r; asm("mov.b64 %0, {%1, %2};" : "=l"(r) : "f"(lo), "f"(hi)); return r;
}
__device__ __forceinline__ void upk2(float& lo, float& hi, u64 v) {
    asm("mov.b64 {%0, %1}, %2;" : "=f"(lo), "=f"(hi) : "l"(v));
}
__device__ __forceinline__ u64 f2fma(u64 a, u64 b, u64 c) {
    u64 r; asm("fma.rn.f32x2 %0, %1, %2, %3;" : "=l"(r) : "l"(a), "l"(b), "l"(c)); return r;
}

// One block, 192 threads: warps 0-4 compute the five 32-length dot products,
// warp 5 loads Wo; fold + write the 4 collapsed scalars to g_c.
__global__ void precompute_kernel(const float* __restrict__ Wt, const float* __restrict__ bt,
                                  const float* __restrict__ Wq, const float* __restrict__ bq,
                                  const float* __restrict__ Wk, const float* __restrict__ bk,
                                  const float* __restrict__ Wv, const float* __restrict__ bv,
                                  const float* __restrict__ Wo, const float* __restrict__ bo) {
    __shared__ float sv[6][32];
    const int warp = threadIdx.x >> 5;
    const int lane = threadIdx.x & 31;

    if (warp < 6) {
        const int e = lane;
        float acc;
        if (warp == 5) {
            acc = Wo[e];
        } else {
            const float* M = (warp == 0 || warp == 3) ? Wq : ((warp == 1) ? Wk : Wv);
            const float* v = (warp < 3) ? Wt : bt;
            acc = 0.f;
#pragma unroll 16
            for (int d = 0; d < 32; d++)
                acc = fmaf(v[d], M[d * 32 + e], acc);
            if (warp == 3) acc += bq[e];
            if (warp == 4) acc += bv[e];
        }
        sv[warp][e] = acc;
    }
    __syncthreads();

    if (warp == 0) {
        const int e = lane;
        const float qv = sv[0][e], kv = sv[1][e], vv = sv[2][e];
        const float qb = sv[3][e], vb = sv[4][e], wo = sv[5][e];
        float a  = qv * kv;
        float c1 = qb * kv;
        float al = vv * wo;
        float be = vb * wo;
#pragma unroll
        for (int off = 16; off > 0; off >>= 1) {
            a  += __shfl_xor_sync(0xffffffffu, a,  off);
            c1 += __shfl_xor_sync(0xffffffffu, c1, off);
            al += __shfl_xor_sync(0xffffffffu, al, off);
            be += __shfl_xor_sync(0xffffffffu, be, off);
        }
        if (e == 0) {
            const float LOG2E = 1.4426950408889634f;
            const float INV_SQRT_D = 0.17677669529663687f;
            g_c = make_float4(a * INV_SQRT_D * LOG2E,
                              c1 * INV_SQRT_D * LOG2E,
                              al * (1.0f / 128.0f),
                              be + bo[0]);
        }
    }
}

// Per warp = one batch row. Double-Chebyshev:
//  x-direction: 24-node Chebyshev quadrature of the empirical measure of the
//    row (moments M_n via T_n recurrence -> weights W_i). Any smooth f then
//    sums as sum_k f(x_k) ~= sum_i W_i f(xnode_i). Cuts ex2 128 -> 24/lane.
//  t-direction: quarter-interval Chebyshev of m(t) (8 nodes/quarter), DCT-8,
//    Clenshaw-7 at the 128 queries (as R13).
#define NX 24
__global__ __launch_bounds__(256) void attn_cheb4_kernel(
    const float* __restrict__ x, float* __restrict__ out, int B) {
    __shared__ float scr[8][32][25];   // per-warp moment partials [lane][n], n=1..24
    __shared__ float Axt[25 * NX];     // Axt[n*24+i]: x-interp DCT weight
    __shared__ float gx[NX];           // x-Chebyshev node positions
    __shared__ float At[64];           // DCT-8 (t-direction)
    __shared__ float Mb[8][25];        // per-warp moments
    __shared__ u64  Wsm[8][NX];        // per-warp packed (W_i, W_i*gamma_i)

    const int tid = threadIdx.x;
    const int warp = tid >> 5;
    const int lane = tid & 31;
    const int b = blockIdx.x * 8 + warp;
    const bool active = (b < B);

    const float PI16 = 0.19634954084936207f;   // pi/16
    const float PI48 = 0.06544984694978735f;   // pi/48

    float4 xv = make_float4(0.f, 0.f, 0.f, 0.f);
    if (active)
        xv = reinterpret_cast<const float4*>(x + (size_t)b * 128)[lane];

    // ---- tables (independent of g_c; overlaps PDL primary) ----
    // Axt[n*24+i] = cos(n*(2i+1)*pi/48) * (n==0 ? 1/24 : 2/24), n=0..24
    for (int idx = tid; idx < 25 * NX; idx += 256) {
        const int n = idx / NX, i = idx - n * NX;
        const int K = (n * (2 * i + 1)) % 96;   // mod 2*pi
        Axt[idx] = cosf_hw((float)K * PI48) * (n == 0 ? (1.0f / 24.0f) : (2.0f / 24.0f));
    }
    if (tid < NX) gx[tid] = cosf_hw((float)(2 * tid + 1) * PI48);
    if (tid < 64) {
        const int j = tid >> 3, i = tid & 7;
        const int K = (i * (2 * j + 1)) & 31;
        At[tid] = cosf_hw((float)K * PI16) * (i == 0 ? 0.125f : 0.25f);
    }
    __syncthreads();
    if (!active) return;

    // row max / min
    float mx = fmaxf(fmaxf(xv.x, xv.y), fmaxf(xv.z, xv.w));
    float mn = fminf(fminf(xv.x, xv.y), fminf(xv.z, xv.w));
#pragma unroll
    for (int off = 16; off > 0; off >>= 1) {
        mx = fmaxf(mx, __shfl_xor_sync(0xffffffffu, mx, off));
        mn = fminf(mn, __shfl_xor_sync(0xffffffffu, mn, off));
    }
    __syncwarp();

    const float cx = 0.5f * (mx + mn);
    const float rx = fmaxf(0.5f * (mx - mn), 1e-5f);
    const float invrx = __fdividef(1.0f, rx);

    // ---- Chebyshev moment partials of this lane's 4 u's ----
    const float u0 = (xv.x - cx) * invrx;
    const float u1 = (xv.y - cx) * invrx;
    const float u2 = (xv.z - cx) * invrx;
    const float u3 = (xv.w - cx) * invrx;
    {
        float* pr = scr[warp][lane];
        const float d0 = u0 + u0, d1 = u1 + u1, d2 = u2 + u2, d3 = u3 + u3;
        float a0 = 1.f, a1 = 1.f, a2 = 1.f, a3 = 1.f;   // T_{n-1}
        float b0 = u0, b1 = u1, b2 = u2, b3 = u3;       // T_n
        pr[1] = ((u0 + u1) + (u2 + u3));
#pragma unroll
        for (int n = 2; n <= 24; n++) {
            const float c0 = fmaf(d0, b0, -a0);
            const float c1 = fmaf(d1, b1, -a1);
            const float c2 = fmaf(d2, b2, -a2);
            const float c3 = fmaf(d3, b3, -a3);
            pr[n] = ((c0 + c1) + (c2 + c3));
            a0 = b0; a1 = b1; a2 = b2; a3 = b3;
            b0 = c0; b1 = c1; b2 = c2; b3 = c3;
        }
    }
    __syncwarp();

    // ---- cross-lane moment reduce: lane n (1..24) sums its column ----
    if (lane >= 1 && lane < 25) {
        float m = 0.f;
#pragma unroll 8
        for (int l = 0; l < 32; l++)
            m += scr[warp][l][lane];
        Mb[warp][lane] = m;
    }
    __syncwarp();

    // ---- quadrature weights: lane i<24: W_i = sum_n Axt[n,i] * M_n ----
    if (lane < NX) {
        float w = Axt[lane] * 128.0f;   // n=0 term: M_0 = 128
#pragma unroll 8
        for (int n = 1; n <= 24; n++)
            w = fmaf(Axt[n * NX + lane], Mb[warp][n], w);
        Wsm[warp][lane] = pk2(w, w * gx[lane]);   // (W, W*gamma)
    }
    __syncwarp();

    // ---- collapsed weights (PDL) ----
    cudaGridDependencySynchronize();
    const float4 c = g_c;
    const float ta = c.x, tc = c.y, alpha = c.z, beta = c.w;

    // t range; 4 quarters
    const float tA = fmaf(ta, mn, tc);
    const float tB = fmaf(ta, mx, tc);
    const float tlo = fminf(tA, tB);
    const float thi = fmaxf(tA, tB);
    const float rad = fmaxf(0.5f * (thi - tlo), 1e-5f);
    const float qw = 0.5f * rad;
    const float rq = 0.25f * rad;
    const float invqw = __fdividef(1.0f, qw);
    const float invrq = 2.0f * invqw;

    // this lane's t-node
    const int ni = lane & 7;
    const float cq = fmaf((float)(lane >> 3) + 0.5f, qw, tlo);
    const float gam = cosf_hw((float)(2 * ni + 1) * PI16);
    const float tj = fmaf(rq, gam, cq);
    const float stab = -((tj > 0.f) ? tj * mx : tj * mn);  // max over [mn,mx] of tj*x

    // ---- node evaluation via 24-point x-quadrature ----
    // arg_i = tj*(cx + rx*g_i) + stab = aj*g_i + bj
    const float aj = tj * rx;
    const float bj = fmaf(tj, cx, stab);
    u64 acc = 0ull;   // (se, dot)
    const u64* wv = Wsm[warp];
#pragma unroll 8
    for (int i = 0; i < NX; i++) {
        const float g = ex2f(fmaf(aj, gx[i], bj));
        acc = f2fma(wv[i], pk2(g, g), acc);
    }
    float se, dot;
    upk2(se, dot, acc);
    const float mj = fmaf(rx, __fdividef(dot, se), cx);  // m at this lane's t-node

    // ---- DCT-8 per quarter ----
    float ci = 0.f;
    const int hbase = lane & 24;
#pragma unroll
    for (int j = 0; j < 8; j++) {
        const float mjj = __shfl_sync(0xffffffffu, mj, hbase + j);
        ci = fmaf(At[j * 8 + ni], mjj, ci);
    }
    // coeff i of quarter q lives in lane q*8 + i

    // ---- Clenshaw-7 at this lane's 4 query points ----
    const float tq0 = fmaf(ta, xv.x, tc);
    const float tq1 = fmaf(ta, xv.y, tc);
    const float tq2 = fmaf(ta, xv.z, tc);
    const float tq3 = fmaf(ta, xv.w, tc);
    const int q0 = min(3, max(0, __float2int_rd((tq0 - tlo) * invqw)));
    const int q1 = min(3, max(0, __float2int_rd((tq1 - tlo) * invqw)));
    const int q2 = min(3, max(0, __float2int_rd((tq2 - tlo) * invqw)));
    const int q3 = min(3, max(0, __float2int_rd((tq3 - tlo) * invqw)));
    const int b0 = q0 << 3, b1 = q1 << 3, b2 = q2 << 3, b3 = q3 << 3;
    const float c0q = fmaf((float)q0 + 0.5f, qw, tlo);
    const float c1q = fmaf((float)q1 + 0.5f, qw, tlo);
    const float c2q = fmaf((float)q2 + 0.5f, qw, tlo);
    const float c3q = fmaf((float)q3 + 0.5f, qw, tlo);
    const float s0 = fminf(1.f, fmaxf(-1.f, (tq0 - c0q) * invrq));
    const float s1 = fminf(1.f, fmaxf(-1.f, (tq1 - c1q) * invrq));
    const float s2 = fminf(1.f, fmaxf(-1.f, (tq2 - c2q) * invrq));
    const float s3 = fminf(1.f, fmaxf(-1.f, (tq3 - c3q) * invrq));
    const float d0 = 2.f * s0, d1 = 2.f * s1, d2 = 2.f * s2, d3 = 2.f * s3;

    float a1_0 = 0.f, a2_0 = 0.f;
    float a1_1 = 0.f, a2_1 = 0.f;
    float a1_2 = 0.f, a2_2 = 0.f;
    float a1_3 = 0.f, a2_3 = 0.f;
#pragma unroll
    for (int i = 7; i >= 1; i--) {
        const float cc0 = __shfl_sync(0xffffffffu, ci, b0 + i);
        const float cc1 = __shfl_sync(0xffffffffu, ci, b1 + i);
        const float cc2 = __shfl_sync(0xffffffffu, ci, b2 + i);
        const float cc3 = __shfl_sync(0xffffffffu, ci, b3 + i);
        float nb;
        nb = fmaf(d0, a1_0, cc0 - a2_0); a2_0 = a1_0; a1_0 = nb;
        nb = fmaf(d1, a1_1, cc1 - a2_1); a2_1 = a1_1; a1_1 = nb;
        nb = fmaf(d2, a1_2, cc2 - a2_2); a2_2 = a1_2; a1_2 = nb;
        nb = fmaf(d3, a1_3, cc3 - a2_3); a2_3 = a1_3; a1_3 = nb;
    }
    const float cz0 = __shfl_sync(0xffffffffu, ci, b0);
    const float cz1 = __shfl_sync(0xffffffffu, ci, b1);
    const float cz2 = __shfl_sync(0xffffffffu, ci, b2);
    const float cz3 = __shfl_sync(0xffffffffu, ci, b3);
    const float m0 = fmaf(s0, a1_0, cz0 - a2_0);
    const float m1 = fmaf(s1, a1_1, cz1 - a2_1);
    const float m2 = fmaf(s2, a1_2, cz2 - a2_2);
    const float m3 = fmaf(s3, a1_3, cz3 - a2_3);

    float msum = (m0 + m1) + (m2 + m3);
#pragma unroll
    for (int off = 16; off > 0; off >>= 1)
        msum += __shfl_xor_sync(0xffffffffu, msum, off);

    if (lane == 0)
        out[b] = fmaf(alpha, msum, beta);
}

extern "C" void kernel_launch(void* const* d_in, const int* in_sizes, int n_in,
                              void* d_out, int out_size) {
    const float* x  = (const float*)d_in[0];
    const float* Wt = (const float*)d_in[1];
    const float* bt = (const float*)d_in[2];
    const float* Wq = (const float*)d_in[3];
    const float* bq = (const float*)d_in[4];
    const float* Wk = (const float*)d_in[5];
    const float* bk = (const float*)d_in[6];
    const float* Wv = (const float*)d_in[7];
    const float* bv = (const float*)d_in[8];
    const float* Wo = (const float*)d_in[9];
    const float* bo = (const float*)d_in[10];
    float* out = (float*)d_out;

    const int B = in_sizes[0] / 128;

    precompute_kernel<<<1, 192>>>(Wt, bt, Wq, bq, Wk, bk, Wv, bv, Wo, bo);

    cudaLaunchConfig_t cfg = {};
    cfg.gridDim = dim3((unsigned)((B + 7) / 8));
    cfg.blockDim = dim3(256);
    cudaLaunchAttribute attr[1];
    attr[0].id = cudaLaunchAttributeProgrammaticStreamSerialization;
    attr[0].val.programmaticStreamSerializationAllowed = 1;
    cfg.attrs = attr;
    cfg.numAttrs = 1;
    cudaLaunchKernelEx(&cfg, attn_cheb4_kernel, x, out, B);
}